// round 17
// baseline (speedup 1.0000x reference)
#include <cuda_runtime.h>
#include <cuda_fp16.h>
#include <cstdint>

// out[65536,64] = xa[65536,256]@wa[256,64] + xb[65536,256]@wb[256,64]
// Single-term fp16: out = fp16(x) @ fp16(w), fp32 accum. rel_err ~2.9e-4.
// mma.sync.m16n8k16.f32.f16.f16.f32, K-PERMUTED fragments (LDG.128 A loads),
// 32-row warps (one B LDS.128 feeds 4 MMAs). BALANCED GRID: 293 CTAs of
// 224 rows (7 warps x 32) -> every SM carries ~2 CTAs (448 rows), killing
// the 2-vs-1 CTA imbalance of the 256-CTA config. Tail CTA warp-guarded.
// Depth-2 register prefetch, no CTA barriers in the loop, 2 CTAs/SM.

#define NCHUNK  32                  // chunks of 16 k
#define M_TILE  224                 // rows per CTA (7 warps x 32)
#define THREADS 224
#define NROWS   65536

// fragment-packed B, uint4 per (t, nj, L), t = 16-k step 0..31:
//   index (t*4+nj)*32 + L; q=L&3, k0 = t*16 + 4q (permuted)
//   x = wh{k0,k0+1}|n_e, y = wh{k0+2,k0+3}|n_e  (n_e = nj*16 + (L>>2))
//   z = wh{k0,k0+1}|n_o, w = wh{k0+2,k0+3}|n_o  (n_o = n_e + 8)
__device__ __align__(16) uint4 g_wfrag[32 * 4 * 32];   // 64 KB

__device__ __forceinline__ uint32_t h2pack(float lo, float hi) {
    uint32_t r;
    asm("cvt.rn.f16x2.f32 %0, %1, %2;" : "=r"(r) : "f"(hi), "f"(lo));
    return r;
}

__device__ __forceinline__ void mma16816(float* c, const uint32_t* a,
                                         uint32_t b0, uint32_t b1) {
    asm volatile(
        "mma.sync.aligned.m16n8k16.row.col.f32.f16.f16.f32 "
        "{%0,%1,%2,%3}, {%4,%5,%6,%7}, {%8,%9}, {%0,%1,%2,%3};"
        : "+f"(c[0]), "+f"(c[1]), "+f"(c[2]), "+f"(c[3])
        : "r"(a[0]), "r"(a[1]), "r"(a[2]), "r"(a[3]), "r"(b0), "r"(b1));
}

// ---- pre-kernel: pack fp16(w), k-permuted, uint4 ni-pairs (proven) ----
__global__ void wconv_kernel(const float* __restrict__ wa,
                             const float* __restrict__ wb) {
    int id = blockIdx.x * 256 + threadIdx.x;   // 0..4095
    int L  = id & 31;
    int nj = (id >> 5) & 3;
    int t  = id >> 7;                          // 16-k step 0..31
    int q  = L & 3;
    int k0 = t * 16 + 4 * q;                   // permuted global k
    const float* __restrict__ w = (k0 < 256) ? wa : wb;
    int kk = k0 & 255;
    int ne = nj * 16 + (L >> 2);
    int no = ne + 8;
    uint4 r;
    r.x = h2pack(w[kk * 64 + ne], w[(kk + 1) * 64 + ne]);
    r.y = h2pack(w[(kk + 2) * 64 + ne], w[(kk + 3) * 64 + ne]);
    r.z = h2pack(w[kk * 64 + no], w[(kk + 1) * 64 + no]);
    r.w = h2pack(w[(kk + 2) * 64 + no], w[(kk + 3) * 64 + no]);
    g_wfrag[id] = r;
}

// ---- main kernel ----
__global__ void __launch_bounds__(THREADS, 2)
sshe_mma_kernel(const float* __restrict__ xa, const float* __restrict__ xb,
                float* __restrict__ out) {
    extern __shared__ uint4 sB[];   // 4096 entries, verbatim g_wfrag
    const int tid = threadIdx.x;
    const int L = tid & 31;
    const int wid = tid >> 5;       // 0..6

    // copy B fragments to smem (identity layout)
    {
        const uint4* src = (const uint4*)g_wfrag;
        for (int i = tid; i < 4096; i += THREADS) sB[i] = src[i];
    }
    __syncthreads();

    // warp's row block; tail CTA may have warps past the end
    const int wrow = blockIdx.x * M_TILE + wid * 32;
    if (wrow >= NROWS) return;      // after the only barrier: safe

    // A coordinates (k-permuted): thread q owns floats [4q, 4q+4) per row
    const int q = L & 3;
    const size_t rA = (size_t)(wrow + (L >> 2));
    const size_t ro[4] = {
        rA * 256 + 4 * q, (rA + 8) * 256 + 4 * q,
        (rA + 16) * 256 + 4 * q, (rA + 24) * 256 + 4 * q};

    float acc[2][8][4];
#pragma unroll
    for (int m = 0; m < 2; m++)
#pragma unroll
        for (int i = 0; i < 8; i++)
#pragma unroll
            for (int j = 0; j < 4; j++) acc[m][i][j] = 0.f;

    float4 st[3][4];
    auto load_chunk = [&](int c, float4* dst) {
        const float* __restrict__ xsrc = (c < 16) ? xa : xb;
        const int kb = (c & 15) * 16;
        dst[0] = *(const float4*)(xsrc + ro[0] + kb);
        dst[1] = *(const float4*)(xsrc + ro[1] + kb);
        dst[2] = *(const float4*)(xsrc + ro[2] + kb);
        dst[3] = *(const float4*)(xsrc + ro[3] + kb);
    };

    // depth-2 register prefetch, fully unrolled
    load_chunk(0, st[0]);
    load_chunk(1, st[1]);

#pragma unroll
    for (int c = 0; c < NCHUNK; c++) {
        if (c + 2 < NCHUNK) load_chunk(c + 2, st[(c + 2) % 3]);
        const float4* v = st[c % 3];

        uint32_t ah0[4], ah1[4];
        ah0[0] = h2pack(v[0].x, v[0].y);
        ah0[1] = h2pack(v[1].x, v[1].y);
        ah0[2] = h2pack(v[0].z, v[0].w);
        ah0[3] = h2pack(v[1].z, v[1].w);
        ah1[0] = h2pack(v[2].x, v[2].y);
        ah1[1] = h2pack(v[3].x, v[3].y);
        ah1[2] = h2pack(v[2].z, v[2].w);
        ah1[3] = h2pack(v[3].z, v[3].w);

        const int base4 = c * 128 + L;
#pragma unroll
        for (int nj = 0; nj < 4; nj++) {
            uint4 B = sB[base4 + nj * 32];   // one LDS.128, feeds 4 MMAs
            mma16816(acc[0][2 * nj], ah0, B.x, B.y);
            mma16816(acc[0][2 * nj + 1], ah0, B.z, B.w);
            mma16816(acc[1][2 * nj], ah1, B.x, B.y);
            mma16816(acc[1][2 * nj + 1], ah1, B.z, B.w);
        }
    }

    // epilogue (proven C mapping, per m-tile)
    const int kk2 = (L & 3) * 2;
#pragma unroll
    for (int mi = 0; mi < 2; mi++) {
        const size_t grow = rA + mi * 16;
#pragma unroll
        for (int ni = 0; ni < 8; ni++) {
            float* o0 = out + grow * 64 + ni * 8 + kk2;
            float* o1 = out + (grow + 8) * 64 + ni * 8 + kk2;
            *(float2*)o0 = make_float2(acc[mi][ni][0], acc[mi][ni][1]);
            *(float2*)o1 = make_float2(acc[mi][ni][2], acc[mi][ni][3]);
        }
    }
}

extern "C" void kernel_launch(void* const* d_in, const int* in_sizes, int n_in,
                              void* d_out, int out_size) {
    const float* xa = (const float*)d_in[0];
    const float* xb = (const float*)d_in[1];
    const float* wa = (const float*)d_in[2];
    const float* wb = (const float*)d_in[3];
    float* out = (float*)d_out;

    cudaFuncSetAttribute(sshe_mma_kernel,
                         cudaFuncAttributeMaxDynamicSharedMemorySize, 65536);

    wconv_kernel<<<16, 256>>>(wa, wb);

    const int nblk = (NROWS + M_TILE - 1) / M_TILE;   // 293
    sshe_mma_kernel<<<nblk, THREADS, 65536>>>(xa, xb, out);
}